// round 4
// baseline (speedup 1.0000x reference)
#include <cuda_runtime.h>
#include <cuda_fp16.h>

// Problem constants
#define NL   8        // layers
#define NH   512      // hidden units per layer
#define NK   16       // fan-in per unit
#define NIN  512      // input width
#define NB   8192     // batch
#define NR   16       // batch rows per block (8 row-pairs, half2 packed)
#define NRP  8        // row pairs
#define WSTORE (NIN + (NL-1)*NH)   // 4096 columns stored (layer-7 outputs go straight to out)
#define VST  9        // smem column stride in half2 words (coprime with 32 banks)

// dynamic smem bytes: values only (4096*9*4 = 147456)
#define SMEM_BYTES (WSTORE*VST*4)

__device__ __forceinline__ float fast_sigmoid(float z) {
    return 1.0f / (1.0f + __expf(-z));
}

__global__ __launch_bounds__(1024, 1)
void ffn_kernel(const float* __restrict__ x,
                const int*   __restrict__ link_idx,
                const float* __restrict__ weights,
                const float* __restrict__ bias,
                float*       __restrict__ out)
{
    extern __shared__ __half2 smem2[];
    __half2* vals2 = smem2;              // [WSTORE][VST] col-major, 8 row-pairs

    const int tid  = threadIdx.x;
    const int lane = tid & 31;
    const int warp = tid >> 5;          // 0..31
    const int rp   = lane & 7;          // row-pair within tile (0..7) -> rows 2rp, 2rp+1
    const int hsub = lane >> 3;         // 0..3
    const int r0   = blockIdx.x * NR;

    // ---- load x tile: rows r0..r0+15, cols 0..511, packed as half2 (two rows per word) ----
    #pragma unroll
    for (int i = tid; i < NRP * NIN; i += 1024) {             // 4096 half2, 4 iters
        int pp = i >> 9;                // row pair 0..7
        int c  = i & (NIN - 1);
        float a = x[(long)(r0 + 2*pp    ) * NIN + c];
        float b = x[(long)(r0 + 2*pp + 1) * NIN + c];
        vals2[c * VST + pp] = __floats2half2_rn(a, b);
    }

    int width = NIN;
    #pragma unroll 1
    for (int l = 0; l < NL; l++) {
        __syncthreads();   // prior layer's values written before this layer gathers

        const float* brow = bias + l * NH;
        const bool last = (l == NL - 1);
        // idx/weights read straight from global: 8 lanes share each address ->
        // dedup'd sectors, L1-resident after the first warp touches them.
        const int4*   gi = (const int4*)  (link_idx + l * NH * NK);
        const float4* gw = (const float4*)(weights  + l * NH * NK);

        #pragma unroll
        for (int p = 0; p < 4; p++) {
            const int h = p * 128 + warp * 4 + hsub;   // 128 h per pass, 4 passes

            const int4*   si = gi + h * 4;
            const float4* sw = gw + h * 4;
            int4   i0 = __ldg(si + 0), i1 = __ldg(si + 1),
                   i2 = __ldg(si + 2), i3 = __ldg(si + 3);
            float4 w0 = __ldg(sw + 0), w1 = __ldg(sw + 1),
                   w2 = __ldg(sw + 2), w3 = __ldg(sw + 3);

            float b0 = __ldg(brow + h);
            float ax0 = b0,   ay0 = b0;
            float ax1 = 0.0f, ay1 = 0.0f;

#define GATHER0(idx, w) { float2 f = __half22float2(vals2[(idx) * VST + rp]); \
                          ax0 = fmaf(f.x, (w), ax0); ay0 = fmaf(f.y, (w), ay0); }
#define GATHER1(idx, w) { float2 f = __half22float2(vals2[(idx) * VST + rp]); \
                          ax1 = fmaf(f.x, (w), ax1); ay1 = fmaf(f.y, (w), ay1); }
            GATHER0(i0.x, w0.x); GATHER1(i0.y, w0.y);
            GATHER0(i0.z, w0.z); GATHER1(i0.w, w0.w);
            GATHER0(i1.x, w1.x); GATHER1(i1.y, w1.y);
            GATHER0(i1.z, w1.z); GATHER1(i1.w, w1.w);
            GATHER0(i2.x, w2.x); GATHER1(i2.y, w2.y);
            GATHER0(i2.z, w2.z); GATHER1(i2.w, w2.w);
            GATHER0(i3.x, w3.x); GATHER1(i3.y, w3.y);
            GATHER0(i3.z, w3.z); GATHER1(i3.w, w3.w);
#undef GATHER0
#undef GATHER1

            float ox = fast_sigmoid(ax0 + ax1);
            float oy = fast_sigmoid(ay0 + ay1);

            if (!last) {
                vals2[(width + h) * VST + rp] = __floats2half2_rn(ox, oy);
            } else {
                out[(long)(r0 + 2*rp    ) * NH + h] = ox;
                out[(long)(r0 + 2*rp + 1) * NH + h] = oy;
            }
        }
        width += NH;
    }
}

extern "C" void kernel_launch(void* const* d_in, const int* in_sizes, int n_in,
                              void* d_out, int out_size)
{
    const float* x        = (const float*)d_in[0];   // (8192, 512) f32
    const int*   link_idx = (const int*)  d_in[1];   // (8, 512, 16) i32
    const float* weights  = (const float*)d_in[2];   // (8, 512, 16) f32
    const float* bias     = (const float*)d_in[3];   // (8, 512) f32
    float*       out      = (float*)d_out;           // (8192, 512) f32

    cudaFuncSetAttribute(ffn_kernel,
                         cudaFuncAttributeMaxDynamicSharedMemorySize, SMEM_BYTES);

    ffn_kernel<<<NB / NR, 1024, SMEM_BYTES>>>(x, link_idx, weights, bias, out);
}

// round 5
// speedup vs baseline: 1.0567x; 1.0567x over previous
#include <cuda_runtime.h>
#include <cuda_fp16.h>

// Problem constants
#define NL   8
#define NH   512
#define NK   16
#define NIN  512
#define NB   8192
#define NR   16        // batch rows per block (8 row-pairs, half2 packed)
#define NRP  8
#define WSTORE (NIN + (NL-1)*NH)   // 4096 stored columns
#define VST  8         // octet-aligned column stride in half2 words: col c -> bank octet (c & 3)
#define ISTR 20        // padded row stride (words) for staged idx/w: conflict-free quads

// values 4096*8*4 = 131072 B ; idx_s 512*20*4 = 40960 ; w_s 40960  -> 212992 B
#define SMEM_BYTES (WSTORE*VST*4 + NH*ISTR*4*2)

// reordered (idx, weight) pairs, written by sched_kernel each launch
__device__ int   g_idx_r[NL*NH*NK];
__device__ float g_w_r  [NL*NH*NK];

// ---------------- scheduling pre-kernel ----------------
// One thread per h-quad (the 4 consecutive h that share each gather instruction).
// Greedily permutes each h's 16 (idx,w) pairs so step t uses 4 columns with
// pairwise-distinct (idx mod 4) -> gathers hit 4 distinct bank octets -> 1 wavefront.
__global__ void sched_kernel(const int* __restrict__ link_idx,
                             const float* __restrict__ weights)
{
    __shared__ int   sidx[64][64];   // [thread][j*16+k]
    __shared__ float sw_s[64][64];

    const int lt = threadIdx.x;               // 0..63
    const int g  = blockIdx.x * 64 + lt;      // group 0..1023
    const int l  = g >> 7;
    const int h0 = (g & 127) * 4;

    const int4*   gi = (const int4*)  (link_idx + (l*NH + h0)*NK);
    const float4* gw = (const float4*)(weights  + (l*NH + h0)*NK);
    #pragma unroll
    for (int m = 0; m < 16; m++) {            // 4 h * 4 int4 each
        *(int4*)  &sidx[lt][m*4] = gi[m];
        *(float4*)&sw_s[lt][m*4] = gw[m];
    }

    // nibble-packed residue counts per h
    unsigned cnt[4];
    unsigned used[4];
    #pragma unroll
    for (int j = 0; j < 4; j++) {
        unsigned c = 0;
        for (int k = 0; k < 16; k++) c += 1u << (4 * (sidx[lt][j*16+k] & 3));
        cnt[j] = c; used[j] = 0;
    }

    for (int t = 0; t < 16; t++) {
        unsigned claimed = 0;
        #pragma unroll
        for (int j = 0; j < 4; j++) {
            int bestr = 0, bests = -2;
            #pragma unroll
            for (int r = 0; r < 4; r++) {
                int c = (int)((cnt[j] >> (4*r)) & 15u);
                int s = (c == 0) ? -1 : (c + (((claimed >> r) & 1u) ? 0 : 16));
                if (s > bests) { bests = s; bestr = r; }
            }
            claimed |= 1u << bestr;
            cnt[j]  -= 1u << (4*bestr);
            int kk = 0;
            for (int k = 0; k < 16; k++) {
                if (!((used[j] >> k) & 1u) && ((sidx[lt][j*16+k] & 3) == bestr)) { kk = k; break; }
            }
            used[j] |= 1u << kk;
            g_idx_r[(l*NH + h0 + j)*NK + t] = sidx[lt][j*16+kk];
            g_w_r  [(l*NH + h0 + j)*NK + t] = sw_s[lt][j*16+kk];
        }
    }
}

__device__ __forceinline__ float fast_sigmoid(float z) {
    return 1.0f / (1.0f + __expf(-z));
}

// ---------------- main fused kernel ----------------
__global__ __launch_bounds__(1024, 1)
void ffn_kernel(const float* __restrict__ x,
                const float* __restrict__ bias,
                float*       __restrict__ out)
{
    extern __shared__ __half2 smem2[];
    __half2* vals2 = smem2;                              // [4096 cols][8 row-pairs], stride 8
    int*     idx_s = (int*)  (smem2 + WSTORE * VST);     // [NH][ISTR]
    float*   w_s   = (float*)(idx_s + NH * ISTR);        // [NH][ISTR]

    const int tid  = threadIdx.x;
    const int lane = tid & 31;
    const int warp = tid >> 5;
    const int rp   = lane & 7;          // row-pair 0..7
    const int hsub = lane >> 3;         // 0..3
    const int r0   = blockIdx.x * NR;

    // ---- x tile: lane mapping (c, pp) -> conflict-free STS (32 distinct banks) ----
    #pragma unroll
    for (int i = tid; i < NRP * NIN; i += 1024) {        // 4096 half2
        int c  = i >> 3;
        int pp = i & 7;
        float a = x[(long)(r0 + 2*pp    ) * NIN + c];
        float b = x[(long)(r0 + 2*pp + 1) * NIN + c];
        vals2[c * VST + pp] = __floats2half2_rn(a, b);
    }

    int width = NIN;
    #pragma unroll 1
    for (int l = 0; l < NL; l++) {
        __syncthreads();   // prior layer reads done + values written

        // ---- stage reordered idx/w into padded smem (conflict-free STS.128) ----
        {
            const int4*   gi = (const int4*)  (g_idx_r + l * NH * NK);
            const float4* gw = (const float4*)(g_w_r   + l * NH * NK);
            #pragma unroll
            for (int i = tid; i < (NH * NK) / 4; i += 1024) {  // 2048 vec4, 2 iters
                int h = i >> 2, m = i & 3;                     // h row, int4 within row
                *(int4*)  (idx_s + h * ISTR + m * 4) = gi[i];
                *(float4*)(w_s   + h * ISTR + m * 4) = gw[i];
            }
        }
        __syncthreads();

        const float* brow = bias + l * NH;
        const bool last = (l == NL - 1);

        #pragma unroll
        for (int p = 0; p < 4; p++) {
            const int h = p * 128 + warp * 4 + hsub;

            // padded rows: the 4 per-warp addresses hit disjoint bank quads -> 1 wf
            const int4*   si = (const int4*)  (idx_s + h * ISTR);
            const float4* sw = (const float4*)(w_s   + h * ISTR);
            int4   i0 = si[0], i1 = si[1], i2 = si[2], i3 = si[3];
            float4 w0 = sw[0], w1 = sw[1], w2 = sw[2], w3 = sw[3];

            float b0 = __ldg(brow + h);
            float ax0 = b0,   ay0 = b0;
            float ax1 = 0.0f, ay1 = 0.0f;

            // each gather step: 4 cols with distinct (idx & 3) -> 32 distinct banks -> 1 wf
#define GATHER0(idx, w) { float2 f = __half22float2(vals2[(idx) * VST + rp]); \
                          ax0 = fmaf(f.x, (w), ax0); ay0 = fmaf(f.y, (w), ay0); }
#define GATHER1(idx, w) { float2 f = __half22float2(vals2[(idx) * VST + rp]); \
                          ax1 = fmaf(f.x, (w), ax1); ay1 = fmaf(f.y, (w), ay1); }
            GATHER0(i0.x, w0.x); GATHER1(i0.y, w0.y);
            GATHER0(i0.z, w0.z); GATHER1(i0.w, w0.w);
            GATHER0(i1.x, w1.x); GATHER1(i1.y, w1.y);
            GATHER0(i1.z, w1.z); GATHER1(i1.w, w1.w);
            GATHER0(i2.x, w2.x); GATHER1(i2.y, w2.y);
            GATHER0(i2.z, w2.z); GATHER1(i2.w, w2.w);
            GATHER0(i3.x, w3.x); GATHER1(i3.y, w3.y);
            GATHER0(i3.z, w3.z); GATHER1(i3.w, w3.w);
#undef GATHER0
#undef GATHER1

            float ox = fast_sigmoid(ax0 + ax1);
            float oy = fast_sigmoid(ay0 + ay1);

            if (!last) {
                // h mod 4 = hsub -> 4 distinct octets x 8 rp -> conflict-free store
                vals2[(width + h) * VST + rp] = __floats2half2_rn(ox, oy);
            } else {
                out[(long)(r0 + 2*rp    ) * NH + h] = ox;
                out[(long)(r0 + 2*rp + 1) * NH + h] = oy;
            }
        }
        width += NH;
    }
}

extern "C" void kernel_launch(void* const* d_in, const int* in_sizes, int n_in,
                              void* d_out, int out_size)
{
    const float* x        = (const float*)d_in[0];   // (8192, 512) f32
    const int*   link_idx = (const int*)  d_in[1];   // (8, 512, 16) i32
    const float* weights  = (const float*)d_in[2];   // (8, 512, 16) f32
    const float* bias     = (const float*)d_in[3];   // (8, 512) f32
    float*       out      = (float*)d_out;           // (8192, 512) f32

    cudaFuncSetAttribute(ffn_kernel,
                         cudaFuncAttributeMaxDynamicSharedMemorySize, SMEM_BYTES);

    sched_kernel<<<16, 64>>>(link_idx, weights);
    ffn_kernel<<<NB / NR, 1024, SMEM_BYTES>>>(x, bias, out);
}

// round 7
// speedup vs baseline: 1.3140x; 1.2435x over previous
#include <cuda_runtime.h>
#include <cuda_fp16.h>
#include <cstdint>

// Problem constants
#define NL   8
#define NH   512
#define NK   16
#define NIN  512
#define NB   8192
#define NR   16        // batch rows per block (8 row-pairs, half2 packed)
#define NRP  8
#define WSTORE (NIN + (NL-1)*NH)   // 4096 stored columns
#define VST  8         // column stride in half2 words: col c -> bank octet (c & 3)

#define STG_ROW   144                  // staged row stride bytes (128 data + 16 pad)
#define STG_WARP  (16*STG_ROW)         // 2304 B per warp
#define SMEM_BYTES (WSTORE*VST*4 + 32*STG_WARP)   // 131072 + 73728 = 204800

// combined idx|w, warp-blocked: [l][warp][row(=p*4+j)][16 idx | 16 w]
__device__ __align__(16) int g_cmb[NL*32*512];

// ---------------- scheduling pre-kernel (bitmask greedy, fast) ----------------
// One thread per h-quad. Permutes each h's 16 (idx,w) pairs so step t uses 4
// columns with pairwise-distinct (idx mod 4) -> gather = 1 smem wavefront.
__global__ void sched_kernel(const int* __restrict__ link_idx,
                             const float* __restrict__ weights)
{
    int q = blockIdx.x * blockDim.x + threadIdx.x;   // 0..1023
    int l  = q >> 7;
    int qq = q & 127;
    int p  = qq >> 5, w = qq & 31;
    int h0 = qq * 4;                                  // == p*128 + w*4

    // position bitmasks per (j, residue)
    unsigned m[4][4];
    #pragma unroll
    for (int j = 0; j < 4; j++) {
        m[j][0] = m[j][1] = m[j][2] = m[j][3] = 0u;
        const int* row = link_idx + (l*NH + h0 + j) * NK;
        #pragma unroll
        for (int k = 0; k < 16; k++)
            m[j][row[k] & 3] |= 1u << k;
    }

    for (int t = 0; t < 16; t++) {
        unsigned claimed = 0;
        #pragma unroll
        for (int j = 0; j < 4; j++) {
            int bestr = 0, bests = -1;
            #pragma unroll
            for (int r = 0; r < 4; r++) {
                int c = __popc(m[j][r]);
                int s = (c == 0) ? -1 : c + (((claimed >> r) & 1u) ? 0 : 16);
                if (s > bests) { bests = s; bestr = r; }
            }
            claimed |= 1u << bestr;
            int kk = __ffs(m[j][bestr]) - 1;
            m[j][bestr] &= m[j][bestr] - 1u;

            const int src = (l*NH + h0 + j) * NK + kk;
            const int dst = (l*32 + w)*512 + (p*4 + j)*32;
            g_cmb[dst + t]      = link_idx[src];
            g_cmb[dst + 16 + t] = __float_as_int(weights[src]);
        }
    }
}

__device__ __forceinline__ float fast_sigmoid(float z) {
    float t;
    asm("tanh.approx.f32 %0, %1;" : "=f"(t) : "f"(0.5f * z));
    return fmaf(0.5f, t, 0.5f);
}

// ---------------- main fused kernel ----------------
__global__ __launch_bounds__(1024, 1)
void ffn_kernel(const float* __restrict__ x,
                const float* __restrict__ bias,
                float*       __restrict__ out)
{
    extern __shared__ __half2 smem2[];
    __half2* vals2 = smem2;                               // [4096 cols][8 rp], stride 8
    char*    stage = (char*)(smem2 + WSTORE * VST);       // 32 warp-private 2304B blocks

    unsigned int stage_u32 =
        (unsigned int)__cvta_generic_to_shared(stage);

    const int tid  = threadIdx.x;
    const int lane = tid & 31;
    const int warp = tid >> 5;
    const int rp   = lane & 7;          // row-pair 0..7
    const int hsub = lane >> 3;         // 0..3
    const int r0   = blockIdx.x * NR;

    // ---- x tile: (c, pp) mapping -> conflict-free STS ----
    #pragma unroll
    for (int i = tid; i < NRP * NIN; i += 1024) {         // 4096 half2
        int c  = i >> 3;
        int pp = i & 7;
        float a = x[(long)(r0 + 2*pp    ) * NIN + c];
        float b = x[(long)(r0 + 2*pp + 1) * NIN + c];
        vals2[c * VST + pp] = __floats2half2_rn(a, b);
    }

    int width = NIN;
    #pragma unroll 1
    for (int l = 0; l < NL; l++) {
        // ---- warp-private staging of this layer's combined idx|w (cp.async) ----
        {
            const int4* src = (const int4*)(g_cmb + (size_t)(l*32 + warp) * 512);
            const unsigned int dstbase = stage_u32 + warp * STG_WARP;
            const int a = lane >> 3, b = lane & 7;
            #pragma unroll
            for (int c = 0; c < 4; c++) {
                int r = c*4 + a;
                unsigned int dst = dstbase + r * STG_ROW + b * 16;
                const int4* s = src + (c*32 + lane);
                asm volatile("cp.async.ca.shared.global [%0], [%1], 16;"
                             :: "r"(dst), "l"(s));
            }
            asm volatile("cp.async.commit_group;" ::: "memory");
        }

        __syncthreads();   // values from previous layer (or x tile) visible
        asm volatile("cp.async.wait_group 0;" ::: "memory");
        __syncwarp();      // staged chunks visible warp-wide

        const float* brow = bias + l * NH;
        const bool last = (l == NL - 1);
        const char* wblk = stage + warp * STG_WARP;

        #pragma unroll
        for (int p = 0; p < 4; p++) {
            const int h = p * 128 + warp * 4 + hsub;
            const char* rowp = wblk + (p*4 + hsub) * STG_ROW;

            // 4 distinct addresses per warp, disjoint bank quads -> 1 wf each
            const int4*   si = (const int4*)  rowp;
            const float4* sw = (const float4*)(rowp + 64);
            int4   i0 = si[0], i1 = si[1], i2 = si[2], i3 = si[3];
            float4 w0 = sw[0], w1 = sw[1], w2 = sw[2], w3 = sw[3];

            float b0 = __ldg(brow + h);
            float ax0 = b0,   ay0 = b0;
            float ax1 = 0.0f, ay1 = 0.0f;

            // scheduled gathers: 4 cols with distinct (idx & 3) -> 1 wavefront
#define GATHER0(idx, w) { float2 f = __half22float2(vals2[(idx) * VST + rp]); \
                          ax0 = fmaf(f.x, (w), ax0); ay0 = fmaf(f.y, (w), ay0); }
#define GATHER1(idx, w) { float2 f = __half22float2(vals2[(idx) * VST + rp]); \
                          ax1 = fmaf(f.x, (w), ax1); ay1 = fmaf(f.y, (w), ay1); }
            GATHER0(i0.x, w0.x); GATHER1(i0.y, w0.y);
            GATHER0(i0.z, w0.z); GATHER1(i0.w, w0.w);
            GATHER0(i1.x, w1.x); GATHER1(i1.y, w1.y);
            GATHER0(i1.z, w1.z); GATHER1(i1.w, w1.w);
            GATHER0(i2.x, w2.x); GATHER1(i2.y, w2.y);
            GATHER0(i2.z, w2.z); GATHER1(i2.w, w2.w);
            GATHER0(i3.x, w3.x); GATHER1(i3.y, w3.y);
            GATHER0(i3.z, w3.z); GATHER1(i3.w, w3.w);
#undef GATHER0
#undef GATHER1

            float ox = fast_sigmoid(ax0 + ax1);
            float oy = fast_sigmoid(ay0 + ay1);

            if (!last) {
                // h mod 4 = hsub -> distinct octets x 8 rp -> conflict-free store
                vals2[(width + h) * VST + rp] = __floats2half2_rn(ox, oy);
            } else {
                out[(long)(r0 + 2*rp    ) * NH + h] = ox;
                out[(long)(r0 + 2*rp + 1) * NH + h] = oy;
            }
        }
        width += NH;
    }
}

extern "C" void kernel_launch(void* const* d_in, const int* in_sizes, int n_in,
                              void* d_out, int out_size)
{
    const float* x        = (const float*)d_in[0];   // (8192, 512) f32
    const int*   link_idx = (const int*)d_in[1];     // (8, 512, 16) i32
    const float* weights  = (const float*)d_in[2];   // (8, 512, 16) f32
    const float* bias     = (const float*)d_in[3];   // (8, 512) f32
    float*       out      = (float*)d_out;           // (8192, 512) f32

    cudaFuncSetAttribute(ffn_kernel,
                         cudaFuncAttributeMaxDynamicSharedMemorySize, SMEM_BYTES);

    sched_kernel<<<32, 32>>>(link_idx, weights);
    ffn_kernel<<<NB / NR, 1024, SMEM_BYTES>>>(x, bias, out);
}